// round 14
// baseline (speedup 1.0000x reference)
#include <cuda_runtime.h>
#include <cstdint>

#define BV     32
#define TT     2048
#define DD     512
#define MAXRUN 1024
#define GBLK   608                  // 152 SMs * 4
#define CTf    0.7f
#define CPTf   0.5f

// ---------------- device scratch (no allocations allowed) ----------------
__device__ float4   g_meta[BV * MAXRUN]; // {start, len, 1/cnt, 1/rep}, compacted quals
__device__ unsigned g_mask[BV * MAXRUN]; // rep bitmask for first 32 rows of each qual run
__device__ float    g_vid_attn[BV];
__device__ int      g_nqual[BV];
__device__ float    g_bsum[GBLK];
__device__ int      g_done;              // reset by last block each launch

// ============================================================================
// Kernel A: run analysis. Unique-writer start/end (no atomics), run-parallel
// stats; emits per-run rep bitmask so kernel B never touches attn.
// ============================================================================
__global__ __launch_bounds__(256) void runAnalysisKernel(const float* __restrict__ attn)
{
    __shared__ float         s_attn[TT];          // 8 KB
    __shared__ unsigned char s_predB[258];        // [0],[257] sentinels
    __shared__ int           s_wTot[8];
    __shared__ int           s_total;
    __shared__ int           s_rstart[MAXRUN];
    __shared__ int           s_rend[MAXRUN];
    __shared__ int           s_wq[8];
    __shared__ float         s_red[8];

    const int b    = blockIdx.x;
    const int tid  = threadIdx.x;
    const int lane = tid & 31;
    const int warp = tid >> 5;
    const float* a_row = attn + (b << 11);

    const float4 v0 = ((const float4*)a_row)[tid * 2];
    const float4 v1 = ((const float4*)a_row)[tid * 2 + 1];
    ((float4*)s_attn)[tid * 2]     = v0;
    ((float4*)s_attn)[tid * 2 + 1] = v1;
    const float av[8] = {v0.x, v0.y, v0.z, v0.w, v1.x, v1.y, v1.z, v1.w};
    unsigned int pb = 0;
    #pragma unroll
    for (int j = 0; j < 8; j++) pb |= (av[j] > CPTf ? 1u : 0u) << j;
    s_predB[tid + 1] = (unsigned char)pb;
    if (tid == 0) { s_predB[0] = 0; s_predB[257] = 0; }
    __syncthreads();

    const unsigned prevB = s_predB[tid];
    const unsigned nextB = s_predB[tid + 2];
    const unsigned carry = (prevB >> 7) & 1u;
    const unsigned nxt   = (nextB & 1u) << 8;
    const unsigned ext   = pb | nxt;
    const unsigned stBits = pb & ~((pb << 1) | carry);
    const unsigned enBits = pb & ~(ext >> 1);

    int pref[8];
    int localTot = 0;
    #pragma unroll
    for (int j = 0; j < 8; j++) {
        localTot += (stBits >> j) & 1;
        pref[j] = localTot;
    }
    int incl = localTot;
    #pragma unroll
    for (int o = 1; o < 32; o <<= 1) {
        int u = __shfl_up_sync(0xffffffffu, incl, o);
        if (lane >= o) incl += u;
    }
    if (lane == 31) s_wTot[warp] = incl;
    __syncthreads();
    if (tid == 0) {
        int acc = 0;
        #pragma unroll
        for (int w = 0; w < 8; w++) { const int v = s_wTot[w]; s_wTot[w] = acc; acc += v; }
        s_total = acc;
    }
    __syncthreads();

    const int threadBase = s_wTot[warp] + (incl - localTot);
    const int base_t = tid * 8;
    #pragma unroll
    for (int j = 0; j < 8; j++) {
        const int rid = threadBase + pref[j] - 1;
        if ((stBits >> j) & 1) s_rstart[rid] = base_t + j;
        if ((enBits >> j) & 1) s_rend[rid]   = base_t + j;
    }
    __syncthreads();

    // ---- run-parallel stats: 4 contiguous runs per thread ----
    const int total = s_total;
    float attnAcc = 0.f;
    int      t0l[4], lenl[4];
    float    irl[4];
    unsigned mskl[4];
    int      q = 0;
    #pragma unroll
    for (int j = 0; j < 4; j++) {
        const int r = 4 * tid + j;
        t0l[j] = 0; lenl[j] = 0; irl[j] = 0.f; mskl[j] = 0u;
        if (r < total) {
            const int t0  = s_rstart[r];
            const int len = s_rend[r] - t0 + 1;
            float sum = 0.f; int rep = 0; unsigned mk = 0u;
            for (int l = 0; l < len; l++) {
                const float a = s_attn[t0 + l];
                sum += a;
                const int isrep = (a > CTf) ? 1 : 0;
                rep += isrep;
                if (l < 32) mk |= ((unsigned)isrep) << l;
            }
            const float mean = sum / (float)len;
            float ssq = 0.f;
            for (int l = 0; l < len; l++) {
                const float d = s_attn[t0 + l] - mean;
                ssq += d * d;
            }
            attnAcc += ssq / (float)len;
            t0l[j]  = t0;
            lenl[j] = len;
            irl[j]  = (rep > 0) ? (1.0f / (float)rep) : 0.0f;
            mskl[j] = mk;
            q += (rep > 0) ? 1 : 0;
        }
    }

    int qi = q;
    #pragma unroll
    for (int o = 1; o < 32; o <<= 1) {
        int u = __shfl_up_sync(0xffffffffu, qi, o);
        if (lane >= o) qi += u;
    }
    if (lane == 31) s_wq[warp] = qi;
    float ar = attnAcc;
    #pragma unroll
    for (int o = 16; o > 0; o >>= 1) ar += __shfl_xor_sync(0xffffffffu, ar, o);
    if (lane == 0) s_red[warp] = ar;
    __syncthreads();
    if (tid == 0) {
        int qa = 0; float asum = 0.f;
        #pragma unroll
        for (int w = 0; w < 8; w++) {
            const int tq = s_wq[w]; s_wq[w] = qa; qa += tq;
            asum += s_red[w];
        }
        g_vid_attn[b] = asum / (float)max(total, 1);
        g_nqual[b]    = qa;
    }
    __syncthreads();
    int slot = s_wq[warp] + (qi - q);
    #pragma unroll
    for (int j = 0; j < 4; j++) {
        if (irl[j] != 0.f) {
            float4 m;
            m.x = __int_as_float(t0l[j]);
            m.y = __int_as_float(lenl[j]);
            m.z = 1.0f / (float)lenl[j];
            m.w = irl[j];
            g_meta[(b << 10) + slot] = m;
            g_mask[(b << 10) + slot] = mskl[j];
            slot++;
        }
    }
}

// ============================================================================
// Kernel B: one warp per (4-run group, quarter-D) over a COMPACT item space.
// t-loop unrolled x2 with all 8 feat loads issued before consumption; coeffs
// come from rep bitmasks (no attn loads). Last-done block finalizes.
// ============================================================================
__global__ __launch_bounds__(256) void featKernel(const float* __restrict__ attn,
                                                  const float* __restrict__ feat,
                                                  float* __restrict__ out)
{
    __shared__ int   s_base[BV + 1];     // item-prefix per video
    __shared__ float s_part[8];
    __shared__ float s_red[8];
    __shared__ int   s_isLast;

    const int tid  = threadIdx.x;
    const int lane = tid & 31;
    const int warp = tid >> 5;

    if (warp == 0) {                      // items_b = 4*ceil(nq/4), prefix scan
        int items = 0;
        if (lane < BV) items = ((g_nqual[lane] + 3) >> 2) << 2;
        int sc = items;
        #pragma unroll
        for (int o = 1; o < 32; o <<= 1) {
            int u = __shfl_up_sync(0xffffffffu, sc, o);
            if (lane >= o) sc += u;
        }
        if (lane < BV) s_base[lane + 1] = sc;
        if (lane == 0) s_base[0] = 0;
    }
    __syncthreads();
    const int totItems = s_base[BV];

    const int gw     = blockIdx.x * 8 + warp;
    const int stride = gridDim.x * 8;
    float ts = 0.f;

    for (int it = gw; it < totItems; it += stride) {
        // binary search video
        int lo = 0, hi = BV;
        #pragma unroll
        for (int step = 0; step < 5; step++) {
            const int mid = (lo + hi) >> 1;
            if (s_base[mid] <= it) lo = mid; else hi = mid;
        }
        const int b    = lo;
        const int rest = it - s_base[b];
        const int g    = rest >> 2;
        const int qtr  = rest & 3;
        const int k0   = g << 2;
        const int nq   = g_nqual[b];
        const int n    = min(4, nq - k0);

        const float4*   mp = g_meta + (b << 10) + k0;
        const unsigned* kp = g_mask + (b << 10) + k0;
        const float4 m0 = __ldg(mp);
        const float4 m1 = (n > 1) ? __ldg(mp + 1) : make_float4(0.f,0.f,0.f,0.f);
        const float4 m2 = (n > 2) ? __ldg(mp + 2) : make_float4(0.f,0.f,0.f,0.f);
        const float4 m3 = (n > 3) ? __ldg(mp + 3) : make_float4(0.f,0.f,0.f,0.f);
        const unsigned M0 = __ldg(kp);
        const unsigned M1 = (n > 1) ? __ldg(kp + 1) : 0u;
        const unsigned M2 = (n > 2) ? __ldg(kp + 2) : 0u;
        const unsigned M3 = (n > 3) ? __ldg(kp + 3) : 0u;

        const int s0 = __float_as_int(m0.x), L0 = __float_as_int(m0.y);
        const int s1 = __float_as_int(m1.x), L1 = (n > 1) ? __float_as_int(m1.y) : 0;
        const int s2 = __float_as_int(m2.x), L2 = (n > 2) ? __float_as_int(m2.y) : 0;
        const int s3 = __float_as_int(m3.x), L3 = (n > 3) ? __float_as_int(m3.y) : 0;

        const float4* fb = (const float4*)feat + ((size_t)(b << 11)) * 128
                         + (qtr << 5) + lane;

        float4 A0 = make_float4(0.f,0.f,0.f,0.f);
        float4 A1 = A0, A2 = A0, A3 = A0;

        int maxL = max(max(L0, L1), max(L2, L3));
        const int lim = min(maxL, 32);

        int j = 0;
        for (; j < lim; j += 2) {
            const int j1 = j + 1;
            const bool p0 = j < L0, q0 = j1 < L0;
            const bool p1 = j < L1, q1 = j1 < L1;
            const bool p2 = j < L2, q2 = j1 < L2;
            const bool p3 = j < L3, q3 = j1 < L3;
            float4 f0a, f0b, f1a, f1b, f2a, f2b, f3a, f3b;
            // issue all loads before any consumption
            if (p0) f0a = __ldg(fb + (size_t)(s0 + j ) * 128);
            if (p1) f1a = __ldg(fb + (size_t)(s1 + j ) * 128);
            if (p2) f2a = __ldg(fb + (size_t)(s2 + j ) * 128);
            if (p3) f3a = __ldg(fb + (size_t)(s3 + j ) * 128);
            if (q0) f0b = __ldg(fb + (size_t)(s0 + j1) * 128);
            if (q1) f1b = __ldg(fb + (size_t)(s1 + j1) * 128);
            if (q2) f2b = __ldg(fb + (size_t)(s2 + j1) * 128);
            if (q3) f3b = __ldg(fb + (size_t)(s3 + j1) * 128);

            if (p0) { const float c = m0.z - (((M0 >> j ) & 1u) ? m0.w : 0.f);
                      A0.x += c*f0a.x; A0.y += c*f0a.y; A0.z += c*f0a.z; A0.w += c*f0a.w; }
            if (q0) { const float c = m0.z - (((M0 >> j1) & 1u) ? m0.w : 0.f);
                      A0.x += c*f0b.x; A0.y += c*f0b.y; A0.z += c*f0b.z; A0.w += c*f0b.w; }
            if (p1) { const float c = m1.z - (((M1 >> j ) & 1u) ? m1.w : 0.f);
                      A1.x += c*f1a.x; A1.y += c*f1a.y; A1.z += c*f1a.z; A1.w += c*f1a.w; }
            if (q1) { const float c = m1.z - (((M1 >> j1) & 1u) ? m1.w : 0.f);
                      A1.x += c*f1b.x; A1.y += c*f1b.y; A1.z += c*f1b.z; A1.w += c*f1b.w; }
            if (p2) { const float c = m2.z - (((M2 >> j ) & 1u) ? m2.w : 0.f);
                      A2.x += c*f2a.x; A2.y += c*f2a.y; A2.z += c*f2a.z; A2.w += c*f2a.w; }
            if (q2) { const float c = m2.z - (((M2 >> j1) & 1u) ? m2.w : 0.f);
                      A2.x += c*f2b.x; A2.y += c*f2b.y; A2.z += c*f2b.z; A2.w += c*f2b.w; }
            if (p3) { const float c = m3.z - (((M3 >> j ) & 1u) ? m3.w : 0.f);
                      A3.x += c*f3a.x; A3.y += c*f3a.y; A3.z += c*f3a.z; A3.w += c*f3a.w; }
            if (q3) { const float c = m3.z - (((M3 >> j1) & 1u) ? m3.w : 0.f);
                      A3.x += c*f3b.x; A3.y += c*f3b.y; A3.z += c*f3b.z; A3.w += c*f3b.w; }
        }
        // exactness tail for runs longer than 32 (uses attn directly)
        if (maxL > 32) {
            const float* arow = attn + (b << 11);
            for (; j < maxL; j++) {
                if (j < L0) {
                    const float a = __ldg(arow + s0 + j);
                    const float4 f = __ldg(fb + (size_t)(s0 + j) * 128);
                    const float c = m0.z - ((a > CTf) ? m0.w : 0.f);
                    A0.x += c*f.x; A0.y += c*f.y; A0.z += c*f.z; A0.w += c*f.w;
                }
                if (j < L1) {
                    const float a = __ldg(arow + s1 + j);
                    const float4 f = __ldg(fb + (size_t)(s1 + j) * 128);
                    const float c = m1.z - ((a > CTf) ? m1.w : 0.f);
                    A1.x += c*f.x; A1.y += c*f.y; A1.z += c*f.z; A1.w += c*f.w;
                }
                if (j < L2) {
                    const float a = __ldg(arow + s2 + j);
                    const float4 f = __ldg(fb + (size_t)(s2 + j) * 128);
                    const float c = m2.z - ((a > CTf) ? m2.w : 0.f);
                    A2.x += c*f.x; A2.y += c*f.y; A2.z += c*f.z; A2.w += c*f.w;
                }
                if (j < L3) {
                    const float a = __ldg(arow + s3 + j);
                    const float4 f = __ldg(fb + (size_t)(s3 + j) * 128);
                    const float c = m3.z - ((a > CTf) ? m3.w : 0.f);
                    A3.x += c*f.x; A3.y += c*f.y; A3.z += c*f.z; A3.w += c*f.w;
                }
            }
        }

        ts += A0.x*A0.x + A0.y*A0.y + A0.z*A0.z + A0.w*A0.w
            + A1.x*A1.x + A1.y*A1.y + A1.z*A1.z + A1.w*A1.w
            + A2.x*A2.x + A2.y*A2.y + A2.z*A2.z + A2.w*A2.w
            + A3.x*A3.x + A3.y*A3.y + A3.z*A3.z + A3.w*A3.w;
    }

    #pragma unroll
    for (int o = 16; o > 0; o >>= 1) ts += __shfl_xor_sync(0xffffffffu, ts, o);
    if (lane == 0) s_part[warp] = ts;
    __syncthreads();
    if (tid == 0) {
        float tot = 0.f;
        #pragma unroll
        for (int w = 0; w < 8; w++) tot += s_part[w];
        g_bsum[blockIdx.x] = tot;
        __threadfence();
        const int old = atomicAdd(&g_done, 1);
        s_isLast = (old == (int)gridDim.x - 1) ? 1 : 0;
    }
    __syncthreads();

    if (s_isLast) {
        __threadfence();
        float acc = 0.f;
        for (int i = tid; i < GBLK; i += 256) acc += g_bsum[i];
        #pragma unroll
        for (int o = 16; o > 0; o >>= 1) acc += __shfl_xor_sync(0xffffffffu, acc, o);
        if (lane == 0) s_red[warp] = acc;
        __syncthreads();
        if (tid == 0) {
            float f = 0.f;
            #pragma unroll
            for (int w = 0; w < 8; w++) f += s_red[w];
            float asum = 0.f; int qs = 0;
            #pragma unroll
            for (int v = 0; v < BV; v++) { asum += g_vid_attn[v]; qs += g_nqual[v]; }
            const float feat_loss = (f * (1.0f / (float)DD)) / (float)max(qs, 1);
            const float attn_loss = asum / (float)BV;
            out[0] = feat_loss + attn_loss;   // FW = AW = 1
            g_done = 0;                       // reset for next graph replay
        }
    }
}

// ============================================================================
extern "C" void kernel_launch(void* const* d_in, const int* in_sizes, int n_in,
                              void* d_out, int out_size)
{
    const float* attn = (const float*)d_in[0];
    const float* feat = (const float*)d_in[1];
    if (n_in >= 2 && in_sizes[0] > in_sizes[1]) {
        const float* tmp = attn; attn = feat; feat = tmp;
    }

    runAnalysisKernel<<<BV, 256>>>(attn);
    featKernel<<<GBLK, 256>>>(attn, feat, (float*)d_out);
}

// round 15
// speedup vs baseline: 1.1792x; 1.1792x over previous
#include <cuda_runtime.h>
#include <cstdint>

#define BV     32
#define TT     2048
#define DD     512
#define MAXRUN 1024
#define GBLK   608                  // 152 SMs * 4
#define RCAP   64                   // max runs staged per block (ceil(32768/608)=54)
#define CTf    0.7f
#define CPTf   0.5f

// ---------------- device scratch (no allocations allowed) ----------------
__device__ float4   g_meta[BV * MAXRUN]; // {start, len, 1/cnt, 1/rep}, per-video compacted
__device__ unsigned g_mask[BV * MAXRUN]; // rep bitmask (first 32 rows of each qual run)
__device__ float    g_vid_attn[BV];
__device__ int      g_nqual[BV];
__device__ float    g_bsum[GBLK];
__device__ int      g_done;              // reset by last block each launch

// ============================================================================
// Kernel A: run analysis. Unique-writer start/end (no atomics), run-parallel
// stats; emits per-run rep bitmask so kernel B rarely touches attn.
// ============================================================================
__global__ __launch_bounds__(256) void runAnalysisKernel(const float* __restrict__ attn)
{
    __shared__ float         s_attn[TT];          // 8 KB
    __shared__ unsigned char s_predB[258];        // [0],[257] sentinels
    __shared__ int           s_wTot[8];
    __shared__ int           s_total;
    __shared__ int           s_rstart[MAXRUN];
    __shared__ int           s_rend[MAXRUN];
    __shared__ int           s_wq[8];
    __shared__ float         s_red[8];

    const int b    = blockIdx.x;
    const int tid  = threadIdx.x;
    const int lane = tid & 31;
    const int warp = tid >> 5;
    const float* a_row = attn + (b << 11);

    const float4 v0 = ((const float4*)a_row)[tid * 2];
    const float4 v1 = ((const float4*)a_row)[tid * 2 + 1];
    ((float4*)s_attn)[tid * 2]     = v0;
    ((float4*)s_attn)[tid * 2 + 1] = v1;
    const float av[8] = {v0.x, v0.y, v0.z, v0.w, v1.x, v1.y, v1.z, v1.w};
    unsigned int pb = 0;
    #pragma unroll
    for (int j = 0; j < 8; j++) pb |= (av[j] > CPTf ? 1u : 0u) << j;
    s_predB[tid + 1] = (unsigned char)pb;
    if (tid == 0) { s_predB[0] = 0; s_predB[257] = 0; }
    __syncthreads();

    const unsigned prevB = s_predB[tid];
    const unsigned nextB = s_predB[tid + 2];
    const unsigned carry = (prevB >> 7) & 1u;
    const unsigned nxt   = (nextB & 1u) << 8;
    const unsigned ext   = pb | nxt;
    const unsigned stBits = pb & ~((pb << 1) | carry);
    const unsigned enBits = pb & ~(ext >> 1);

    int pref[8];
    int localTot = 0;
    #pragma unroll
    for (int j = 0; j < 8; j++) {
        localTot += (stBits >> j) & 1;
        pref[j] = localTot;
    }
    int incl = localTot;
    #pragma unroll
    for (int o = 1; o < 32; o <<= 1) {
        int u = __shfl_up_sync(0xffffffffu, incl, o);
        if (lane >= o) incl += u;
    }
    if (lane == 31) s_wTot[warp] = incl;
    __syncthreads();
    if (tid == 0) {
        int acc = 0;
        #pragma unroll
        for (int w = 0; w < 8; w++) { const int v = s_wTot[w]; s_wTot[w] = acc; acc += v; }
        s_total = acc;
    }
    __syncthreads();

    const int threadBase = s_wTot[warp] + (incl - localTot);
    const int base_t = tid * 8;
    #pragma unroll
    for (int j = 0; j < 8; j++) {
        const int rid = threadBase + pref[j] - 1;
        if ((stBits >> j) & 1) s_rstart[rid] = base_t + j;
        if ((enBits >> j) & 1) s_rend[rid]   = base_t + j;
    }
    __syncthreads();

    // ---- run-parallel stats: 4 contiguous runs per thread ----
    const int total = s_total;
    float attnAcc = 0.f;
    int      t0l[4], lenl[4];
    float    irl[4];
    unsigned mskl[4];
    int      q = 0;
    #pragma unroll
    for (int j = 0; j < 4; j++) {
        const int r = 4 * tid + j;
        t0l[j] = 0; lenl[j] = 0; irl[j] = 0.f; mskl[j] = 0u;
        if (r < total) {
            const int t0  = s_rstart[r];
            const int len = s_rend[r] - t0 + 1;
            float sum = 0.f; int rep = 0; unsigned mk = 0u;
            for (int l = 0; l < len; l++) {
                const float a = s_attn[t0 + l];
                sum += a;
                const int isrep = (a > CTf) ? 1 : 0;
                rep += isrep;
                if (l < 32) mk |= ((unsigned)isrep) << l;
            }
            const float mean = sum / (float)len;
            float ssq = 0.f;
            for (int l = 0; l < len; l++) {
                const float d = s_attn[t0 + l] - mean;
                ssq += d * d;
            }
            attnAcc += ssq / (float)len;
            t0l[j]  = t0;
            lenl[j] = len;
            irl[j]  = (rep > 0) ? (1.0f / (float)rep) : 0.0f;
            mskl[j] = mk;
            q += (rep > 0) ? 1 : 0;
        }
    }

    int qi = q;
    #pragma unroll
    for (int o = 1; o < 32; o <<= 1) {
        int u = __shfl_up_sync(0xffffffffu, qi, o);
        if (lane >= o) qi += u;
    }
    if (lane == 31) s_wq[warp] = qi;
    float ar = attnAcc;
    #pragma unroll
    for (int o = 16; o > 0; o >>= 1) ar += __shfl_xor_sync(0xffffffffu, ar, o);
    if (lane == 0) s_red[warp] = ar;
    __syncthreads();
    if (tid == 0) {
        int qa = 0; float asum = 0.f;
        #pragma unroll
        for (int w = 0; w < 8; w++) {
            const int tq = s_wq[w]; s_wq[w] = qa; qa += tq;
            asum += s_red[w];
        }
        g_vid_attn[b] = asum / (float)max(total, 1);
        g_nqual[b]    = qa;
    }
    __syncthreads();
    int slot = s_wq[warp] + (qi - q);
    #pragma unroll
    for (int j = 0; j < 4; j++) {
        if (irl[j] != 0.f) {
            float4 m;
            m.x = __int_as_float(t0l[j]);
            m.y = __int_as_float(lenl[j]);
            m.z = 1.0f / (float)lenl[j];
            m.w = irl[j];
            g_meta[(b << 10) + slot] = m;
            g_mask[(b << 10) + slot] = mskl[j];
            slot++;
        }
    }
}

// ============================================================================
// Kernel B: block-cooperative metadata staging. Each block owns a contiguous
// range of globally-indexed qual runs; metas/masks staged to shared in one
// parallel round. Warps consume (run x quarter-D) units from shared, two
// units at a time (4 independent feat loads per iteration).
// ============================================================================
__global__ __launch_bounds__(256) void featKernel(const float* __restrict__ attn,
                                                  const float* __restrict__ feat,
                                                  float* __restrict__ out)
{
    __shared__ int      s_qbase[BV + 1];
    __shared__ float4   s_meta[RCAP];
    __shared__ unsigned s_mask[RCAP];
    __shared__ int      s_vid[RCAP];
    __shared__ float    s_part[8];
    __shared__ float    s_red[8];
    __shared__ int      s_isLast;

    const int tid  = threadIdx.x;
    const int lane = tid & 31;
    const int warp = tid >> 5;

    if (warp == 0) {                      // prefix of qual counts
        int nq = (lane < BV) ? g_nqual[lane] : 0;
        int sc = nq;
        #pragma unroll
        for (int o = 1; o < 32; o <<= 1) {
            int u = __shfl_up_sync(0xffffffffu, sc, o);
            if (lane >= o) sc += u;
        }
        if (lane < BV) s_qbase[lane + 1] = sc;
        if (lane == 0) s_qbase[0] = 0;
    }
    __syncthreads();
    const int Q      = s_qbase[BV];
    const int perBlk = (Q + (int)gridDim.x - 1) / (int)gridDim.x;
    const int r0     = blockIdx.x * perBlk;
    const int r1     = min(r0 + perBlk, Q);
    const int nr     = max(r1 - r0, 0);

    // ---- cooperative staging: one LDG round for all metas in range ----
    for (int i = tid; i < nr; i += 256) {
        const int g = r0 + i;
        int lo = 0, hi = BV;
        #pragma unroll
        for (int step = 0; step < 5; step++) {
            const int mid = (lo + hi) >> 1;
            if (s_qbase[mid] <= g) lo = mid; else hi = mid;
        }
        const int k = g - s_qbase[lo];
        s_meta[i] = __ldg(g_meta + (lo << 10) + k);
        s_mask[i] = __ldg(g_mask + (lo << 10) + k);
        s_vid[i]  = lo;
    }
    __syncthreads();

    // ---- units: (staged run, quarter). Warp processes 2 units at once. ----
    const int units = nr << 2;
    float ts = 0.f;

    for (int p = warp; (p << 1) < units; p += 8) {
        const int u0 = p << 1;
        const int u1 = u0 + 1;             // u1 < units always (units is even)
        const int i0 = u0 >> 2, q0 = u0 & 3;
        const int i1 = u1 >> 2, q1 = u1 & 3;

        const float4   m0 = s_meta[i0];
        const float4   m1 = s_meta[i1];
        const unsigned M0 = s_mask[i0];
        const unsigned M1 = s_mask[i1];
        const int      b0 = s_vid[i0];
        const int      b1 = s_vid[i1];

        const int sA = __float_as_int(m0.x), LA = __float_as_int(m0.y);
        const int sB = __float_as_int(m1.x), LB = __float_as_int(m1.y);

        const float4* fbA = (const float4*)feat + ((size_t)((b0 << 11) + sA)) * 128
                          + (q0 << 5) + lane;
        const float4* fbB = (const float4*)feat + ((size_t)((b1 << 11) + sB)) * 128
                          + (q1 << 5) + lane;

        float4 A = make_float4(0.f, 0.f, 0.f, 0.f);
        float4 B = A;

        const int limA = min(LA, 32), limB = min(LB, 32);
        const int lim  = max(limA, limB);

        int j = 0;
        for (; j + 2 <= lim; j += 2) {
            const bool a0 = j < limA, a1 = (j + 1) < limA;
            const bool c0 = j < limB, c1 = (j + 1) < limB;
            float4 fA0, fA1, fB0, fB1;
            if (a0) fA0 = __ldg(fbA + (size_t)j       * 128);
            if (c0) fB0 = __ldg(fbB + (size_t)j       * 128);
            if (a1) fA1 = __ldg(fbA + (size_t)(j + 1) * 128);
            if (c1) fB1 = __ldg(fbB + (size_t)(j + 1) * 128);
            if (a0) { const float c = m0.z - (((M0 >> j)     & 1u) ? m0.w : 0.f);
                      A.x += c*fA0.x; A.y += c*fA0.y; A.z += c*fA0.z; A.w += c*fA0.w; }
            if (a1) { const float c = m0.z - (((M0 >> (j+1)) & 1u) ? m0.w : 0.f);
                      A.x += c*fA1.x; A.y += c*fA1.y; A.z += c*fA1.z; A.w += c*fA1.w; }
            if (c0) { const float c = m1.z - (((M1 >> j)     & 1u) ? m1.w : 0.f);
                      B.x += c*fB0.x; B.y += c*fB0.y; B.z += c*fB0.z; B.w += c*fB0.w; }
            if (c1) { const float c = m1.z - (((M1 >> (j+1)) & 1u) ? m1.w : 0.f);
                      B.x += c*fB1.x; B.y += c*fB1.y; B.z += c*fB1.z; B.w += c*fB1.w; }
        }
        if (j < lim) {                     // odd leftover within 32
            if (j < limA) {
                const float4 f = __ldg(fbA + (size_t)j * 128);
                const float c = m0.z - (((M0 >> j) & 1u) ? m0.w : 0.f);
                A.x += c*f.x; A.y += c*f.y; A.z += c*f.z; A.w += c*f.w;
            }
            if (j < limB) {
                const float4 f = __ldg(fbB + (size_t)j * 128);
                const float c = m1.z - (((M1 >> j) & 1u) ? m1.w : 0.f);
                B.x += c*f.x; B.y += c*f.y; B.z += c*f.z; B.w += c*f.w;
            }
            j = lim;
        }
        // exactness tail for runs longer than 32 (uses attn directly)
        const int maxL = max(LA, LB);
        if (maxL > 32) {
            for (; j < maxL; j++) {
                if (j < LA) {
                    const float a = __ldg(attn + (b0 << 11) + sA + j);
                    const float4 f = __ldg(fbA + (size_t)j * 128);
                    const float c = m0.z - ((a > CTf) ? m0.w : 0.f);
                    A.x += c*f.x; A.y += c*f.y; A.z += c*f.z; A.w += c*f.w;
                }
                if (j < LB) {
                    const float a = __ldg(attn + (b1 << 11) + sB + j);
                    const float4 f = __ldg(fbB + (size_t)j * 128);
                    const float c = m1.z - ((a > CTf) ? m1.w : 0.f);
                    B.x += c*f.x; B.y += c*f.y; B.z += c*f.z; B.w += c*f.w;
                }
            }
        }

        ts += A.x*A.x + A.y*A.y + A.z*A.z + A.w*A.w
            + B.x*B.x + B.y*B.y + B.z*B.z + B.w*B.w;
    }

    #pragma unroll
    for (int o = 16; o > 0; o >>= 1) ts += __shfl_xor_sync(0xffffffffu, ts, o);
    if (lane == 0) s_part[warp] = ts;
    __syncthreads();
    if (tid == 0) {
        float tot = 0.f;
        #pragma unroll
        for (int w = 0; w < 8; w++) tot += s_part[w];
        g_bsum[blockIdx.x] = tot;
        __threadfence();
        const int old = atomicAdd(&g_done, 1);
        s_isLast = (old == (int)gridDim.x - 1) ? 1 : 0;
    }
    __syncthreads();

    if (s_isLast) {
        __threadfence();
        float acc = 0.f;
        for (int i = tid; i < GBLK; i += 256) acc += g_bsum[i];
        #pragma unroll
        for (int o = 16; o > 0; o >>= 1) acc += __shfl_xor_sync(0xffffffffu, acc, o);
        if (lane == 0) s_red[warp] = acc;
        __syncthreads();
        if (tid == 0) {
            float f = 0.f;
            #pragma unroll
            for (int w = 0; w < 8; w++) f += s_red[w];
            float asum = 0.f; int qs = 0;
            #pragma unroll
            for (int v = 0; v < BV; v++) { asum += g_vid_attn[v]; qs += g_nqual[v]; }
            const float feat_loss = (f * (1.0f / (float)DD)) / (float)max(qs, 1);
            const float attn_loss = asum / (float)BV;
            out[0] = feat_loss + attn_loss;   // FW = AW = 1
            g_done = 0;                       // reset for next graph replay
        }
    }
}

// ============================================================================
extern "C" void kernel_launch(void* const* d_in, const int* in_sizes, int n_in,
                              void* d_out, int out_size)
{
    const float* attn = (const float*)d_in[0];
    const float* feat = (const float*)d_in[1];
    if (n_in >= 2 && in_sizes[0] > in_sizes[1]) {
        const float* tmp = attn; attn = feat; feat = tmp;
    }

    runAnalysisKernel<<<BV, 256>>>(attn);
    featKernel<<<GBLK, 256>>>(attn, feat, (float*)d_out);
}